// round 16
// baseline (speedup 1.0000x reference)
#include <cuda_runtime.h>
#include <stdint.h>

// Problem constants (fixed shapes per reference)
constexpr int D      = 256;    // IN_CHANNELS
constexpr int NPER   = 100;    // nodes per graph
constexpr int KSEL   = 50;     // ceil(0.5 * 100)
constexpr int NGRAPH = 1000;   // 100000 / 100
constexpr int PSTRIDE = 17;    // 16 partials + 1 pad -> conflict-free column sums

// out layout (float32, 150000 elems):
//   [0      , 50000)  node_index  (as float)
//   [50000  , 100000) cluster_index (= arange)
//   [100000 , 150000) weight (scores of selected nodes)

__global__ __launch_bounds__(256) void selectsparse_kernel(
    const float* __restrict__ x,
    const float* __restrict__ W,
    const float* __restrict__ b,
    float* __restrict__ out)
{
    __shared__ float s_part[NPER * PSTRIDE];   // [node][half-lane] partial sums
    __shared__ float s_scores[NPER];

    const int g    = blockIdx.x;
    const int tid  = threadIdx.x;
    const int lane = tid & 31;
    const int warp = tid >> 5;

    // Each lane holds its 8-float slice of W in registers (tiny, L2-hot).
    const float4 w0 = reinterpret_cast<const float4*>(W)[lane * 2 + 0];
    const float4 w1 = reinterpret_cast<const float4*>(W)[lane * 2 + 1];
    const float bias = b[0];

    const float4* xg = reinterpret_cast<const float4*>(x + (size_t)g * NPER * D);

    // Warp w handles node pair {2w, 2w+1}, striding by 16 (proven pattern:
    // 4 independent LDG.128 per lane, front-batched by ptxas).
    // One xor-fold (offset 16), then lanes 0-15 fire 16-elem partials into
    // smem via STS. The shfl is off the critical path: next-iteration LDGs
    // are independent and issue while it drains.
    for (int n = warp * 2; n < NPER; n += 16) {
        const int n2 = n + 1;
        const float4* rowA = xg + n * (D / 4);
        const float4* rowB = rowA + (D / 4);   // n2 = n+1 always valid (100 even)
        float4 a0 = rowA[lane * 2 + 0];
        float4 a1 = rowA[lane * 2 + 1];
        float4 b0 = rowB[lane * 2 + 0];
        float4 b1 = rowB[lane * 2 + 1];
        float sA = a0.x * w0.x + a0.y * w0.y + a0.z * w0.z + a0.w * w0.w
                 + a1.x * w1.x + a1.y * w1.y + a1.z * w1.z + a1.w * w1.w;
        float sB = b0.x * w0.x + b0.y * w0.y + b0.z * w0.z + b0.w * w0.w
                 + b1.x * w1.x + b1.y * w1.y + b1.z * w1.z + b1.w * w1.w;
        sA += __shfl_xor_sync(0xffffffffu, sA, 16);
        sB += __shfl_xor_sync(0xffffffffu, sB, 16);
        if (lane < 16) {
            s_part[n  * PSTRIDE + lane] = sA;
            s_part[n2 * PSTRIDE + lane] = sB;
        }
    }
    __syncthreads();   // drains pending STS

    // Cross-lane sum: thread t sums its node's 16 partials.
    // Stride-17 rows -> lanes hit distinct banks at every step (conflict-free).
    if (tid < NPER) {
        const float* p = &s_part[tid * PSTRIDE];
        float s = bias;
        #pragma unroll
        for (int j = 0; j < 16; j += 4) {   // 4-way ILP over independent LDS
            s += p[j] + p[j + 1] + p[j + 2] + p[j + 3];
        }
        s_scores[tid] = s;
    }
    __syncthreads();

    // Rank selection: rank(t) = #{j ordered before t} under descending score
    // with ascending-index tie-break -> unique rank in [0,100), identical
    // ordering to lax.top_k. rank < 50 -> emit at slot rank.
    if (tid < NPER) {
        const float st = s_scores[tid];
        int r = 0;
        #pragma unroll 4
        for (int j = 0; j < NPER; j++) {
            const float sj = s_scores[j];   // broadcast LDS, conflict-free
            r += (sj > st) | ((sj == st) & (j < tid));
        }
        if (r < KSEL) {
            const int node = g * NPER + tid;
            const int cl   = g * KSEL + r;
            out[cl]                     = (float)node;
            out[NGRAPH * KSEL + cl]     = (float)cl;
            out[2 * NGRAPH * KSEL + cl] = st;
        }
    }
}

extern "C" void kernel_launch(void* const* d_in, const int* in_sizes, int n_in,
                              void* d_out, int out_size) {
    // Identify inputs by element count (robust to metadata ordering):
    //   x: 25,600,000 f32 | batch: 100,000 (unused) | W: 256 | b: 1
    const float* x = nullptr;
    const float* W = nullptr;
    const float* b = nullptr;
    for (int i = 0; i < n_in; i++) {
        if      (in_sizes[i] == NGRAPH * NPER * D) x = (const float*)d_in[i];
        else if (in_sizes[i] == D)                 W = (const float*)d_in[i];
        else if (in_sizes[i] == 1)                 b = (const float*)d_in[i];
    }
    if (!x) x = (const float*)d_in[0];
    if (!W) W = (const float*)d_in[2];
    if (!b) b = (const float*)d_in[3];
    (void)out_size;
    selectsparse_kernel<<<NGRAPH, 256>>>(x, W, b, (float*)d_out);
}

// round 17
// speedup vs baseline: 1.0152x; 1.0152x over previous
#include <cuda_runtime.h>
#include <stdint.h>

// Problem constants (fixed shapes per reference)
constexpr int D      = 256;    // IN_CHANNELS
constexpr int NPER   = 100;    // nodes per graph
constexpr int KSEL   = 50;     // ceil(0.5 * 100)
constexpr int NGRAPH = 1000;   // 100000 / 100
constexpr int PSTRIDE = 33;    // 32 partials + 1 pad -> conflict-free column sums

// out layout (float32, 150000 elems):
//   [0      , 50000)  node_index  (as float)
//   [50000  , 100000) cluster_index (= arange)
//   [100000 , 150000) weight (scores of selected nodes)

__global__ __launch_bounds__(256) void selectsparse_kernel(
    const float* __restrict__ x,
    const float* __restrict__ W,
    const float* __restrict__ b,
    float* __restrict__ out)
{
    __shared__ float s_part[NPER * PSTRIDE];   // [node][lane] partial sums
    __shared__ float s_scores[NPER];

    const int g    = blockIdx.x;
    const int tid  = threadIdx.x;
    const int lane = tid & 31;
    const int warp = tid >> 5;

    // Each lane holds its 8-float slice of W in registers (tiny, L2-hot).
    const float4 w0 = reinterpret_cast<const float4*>(W)[lane * 2 + 0];
    const float4 w1 = reinterpret_cast<const float4*>(W)[lane * 2 + 1];
    const float bias = b[0];

    const float4* xg = reinterpret_cast<const float4*>(x + (size_t)g * NPER * D);

    // Warp w handles node pair {2w, 2w+1}, striding by 16 (proven pattern:
    // 4 independent LDG.128 per lane, front-batched by ptxas).
    // NO in-loop reduction: each lane fires its 8-elem partial into smem via
    // STS (issue-only, no result latency, distinct addresses). The warp goes
    // straight back to loading — zero shfl dead time.
    for (int n = warp * 2; n < NPER; n += 16) {
        const int n2 = n + 1;
        const float4* rowA = xg + n * (D / 4);
        const float4* rowB = rowA + (D / 4);   // n2 = n+1 always valid (100 even)
        float4 a0 = rowA[lane * 2 + 0];
        float4 a1 = rowA[lane * 2 + 1];
        float4 b0 = rowB[lane * 2 + 0];
        float4 b1 = rowB[lane * 2 + 1];
        float sA = a0.x * w0.x + a0.y * w0.y + a0.z * w0.z + a0.w * w0.w
                 + a1.x * w1.x + a1.y * w1.y + a1.z * w1.z + a1.w * w1.w;
        float sB = b0.x * w0.x + b0.y * w0.y + b0.z * w0.z + b0.w * w0.w
                 + b1.x * w1.x + b1.y * w1.y + b1.z * w1.z + b1.w * w1.w;
        s_part[n  * PSTRIDE + lane] = sA;
        s_part[n2 * PSTRIDE + lane] = sB;
    }
    __syncthreads();   // drains pending STS

    // Cross-lane sum moved here: thread t sums its node's 32 partials.
    // Stride-33 rows -> lanes read distinct banks at every step (conflict-free).
    if (tid < NPER) {
        const float* p = &s_part[tid * PSTRIDE];
        float s = bias;
        #pragma unroll
        for (int j = 0; j < 32; j += 4) {   // 4-way ILP over independent LDS
            s += p[j] + p[j + 1] + p[j + 2] + p[j + 3];
        }
        s_scores[tid] = s;
    }
    __syncthreads();

    // Rank selection: rank(t) = #{j ordered before t} under descending score
    // with ascending-index tie-break -> unique rank in [0,100), identical
    // ordering to lax.top_k. rank < 50 -> emit at slot rank.
    if (tid < NPER) {
        const float st = s_scores[tid];
        int r = 0;
        #pragma unroll 4
        for (int j = 0; j < NPER; j++) {
            const float sj = s_scores[j];   // broadcast LDS, conflict-free
            r += (sj > st) | ((sj == st) & (j < tid));
        }
        if (r < KSEL) {
            const int node = g * NPER + tid;
            const int cl   = g * KSEL + r;
            out[cl]                     = (float)node;
            out[NGRAPH * KSEL + cl]     = (float)cl;
            out[2 * NGRAPH * KSEL + cl] = st;
        }
    }
}

extern "C" void kernel_launch(void* const* d_in, const int* in_sizes, int n_in,
                              void* d_out, int out_size) {
    // Identify inputs by element count (robust to metadata ordering):
    //   x: 25,600,000 f32 | batch: 100,000 (unused) | W: 256 | b: 1
    const float* x = nullptr;
    const float* W = nullptr;
    const float* b = nullptr;
    for (int i = 0; i < n_in; i++) {
        if      (in_sizes[i] == NGRAPH * NPER * D) x = (const float*)d_in[i];
        else if (in_sizes[i] == D)                 W = (const float*)d_in[i];
        else if (in_sizes[i] == 1)                 b = (const float*)d_in[i];
    }
    if (!x) x = (const float*)d_in[0];
    if (!W) W = (const float*)d_in[2];
    if (!b) b = (const float*)d_in[3];
    (void)out_size;
    selectsparse_kernel<<<NGRAPH, 256>>>(x, W, b, (float*)d_out);
}